// round 15
// baseline (speedup 1.0000x reference)
#include <cuda_runtime.h>
#include <cuda_bf16.h>
#include <math.h>

#define B_ 256
#define T_ 1024
#define V_ 96
#define H_ 128

typedef unsigned long long ull;
typedef unsigned int uint;

// Device-global scratch (allocation-free per harness rules)
__device__ __align__(16) float g_proj[V_ * H_];    // emb @ W_ih0^T + b_ih0 + b_hh0
__device__ __align__(16) float g_y1[B_ * T_ * H_]; // layer-1 outputs (fc input)
__device__ __align__(16) uint g_Wfhi[V_ * 64];     // fcW split hi (bf16x2, [n][64])
__device__ __align__(16) uint g_Wflo[V_ * 64];     // fcW split lo

__device__ __forceinline__ ull ffma2(ull a, ull b, ull c) {
    ull d;
    asm("fma.rn.f32x2 %0, %1, %2, %3;" : "=l"(d) : "l"(a), "l"(b), "l"(c));
    return d;
}
__device__ __forceinline__ ull fadd2(ull a, ull b) {
    ull d;
    asm("add.rn.f32x2 %0, %1, %2;" : "=l"(d) : "l"(a), "l"(b));
    return d;
}
__device__ __forceinline__ float hadd(ull a) {
    float x, y;
    asm("mov.b64 {%0, %1}, %2;" : "=f"(x), "=f"(y) : "l"(a));
    return x + y;
}
__device__ __forceinline__ float tanh_fast(float x) {
    float y;
    asm("tanh.approx.f32 %0, %1;" : "=f"(y) : "f"(x));
    return y;
}
__device__ __forceinline__ void split_pack(float2 v, uint& hi, uint& lo) {
    __nv_bfloat16 h0 = __float2bfloat16_rn(v.x);
    __nv_bfloat16 h1 = __float2bfloat16_rn(v.y);
    float r0 = v.x - __bfloat162float(h0);
    float r1 = v.y - __bfloat162float(h1);
    __nv_bfloat162 hp; hp.x = h0; hp.y = h1;
    __nv_bfloat162 lp = __floats2bfloat162_rn(r0, r1);
    hi = *(uint*)&hp;
    lo = *(uint*)&lp;
}

// ---------------------------------------------------------------------------
// Projected embedding table: g_proj[v][j] = sum_h emb[v][h]*W_ih0[j][h] + b
// ---------------------------------------------------------------------------
__global__ void k_proj(const float* __restrict__ emb, const float* __restrict__ Wih0,
                       const float* __restrict__ bih0, const float* __restrict__ bhh0) {
    __shared__ float er[H_];
    int v = blockIdx.x, j = threadIdx.x;
    er[j] = emb[v * H_ + j];
    __syncthreads();
    float s = bih0[j] + bhh0[j];
    const float* wr = Wih0 + j * H_;
#pragma unroll 8
    for (int h = 0; h < H_; h++) s += er[h] * wr[h];
    g_proj[v * H_ + j] = s;
}

// Pre-split fc weights into bf16 hi/lo planes.
__global__ void k_wsplit(const float* __restrict__ W, uint* __restrict__ hi,
                         uint* __restrict__ lo, int npairs) {
    int i = blockIdx.x * 256 + threadIdx.x;
    if (i >= npairs) return;
    uint h, l;
    split_pack(((const float2*)W)[i], h, l);
    hi[i] = h;
    lo[i] = l;
}

// ---------------------------------------------------------------------------
// Fused 2-layer recurrence. Persistent: grid 128, 384 thr, 2 batches/CTA.
// Groups (gid = tid>>7): G0 l0-step, G1 l1 input proj, G2 l1 recurrent+tanh.
// Software pipeline (lag 2): iter i forms h0[i], u[i-1], h1[i-2].
// ONE __syncthreads per iteration. All dots exact fp32 (FFMA2), FULL K=128.
// ---------------------------------------------------------------------------
__device__ __forceinline__ void dot2b(const float* __restrict__ hA,
                                      const float* __restrict__ hB,
                                      const ull* w, float& pA, float& pB) {
    const ulonglong2* a2 = (const ulonglong2*)hA;
    const ulonglong2* b2 = (const ulonglong2*)hB;
    ull aA0 = 0, aA1 = 0, aA2 = 0, aA3 = 0;
    ull aB0 = 0, aB1 = 0, aB2 = 0, aB3 = 0;
#pragma unroll
    for (int i = 0; i < 32; i += 2) {           // 32 chunks x 4 floats = full K=128
        ulonglong2 vA0 = a2[i],     vB0 = b2[i];
        ulonglong2 vA1 = a2[i + 1], vB1 = b2[i + 1];
        aA0 = ffma2(w[2 * i],     vA0.x, aA0);
        aB0 = ffma2(w[2 * i],     vB0.x, aB0);
        aA1 = ffma2(w[2 * i + 1], vA0.y, aA1);
        aB1 = ffma2(w[2 * i + 1], vB0.y, aB1);
        aA2 = ffma2(w[2 * i + 2], vA1.x, aA2);
        aB2 = ffma2(w[2 * i + 2], vB1.x, aB2);
        aA3 = ffma2(w[2 * i + 3], vA1.y, aA3);
        aB3 = ffma2(w[2 * i + 3], vB1.y, aB3);
    }
    pA = hadd(fadd2(fadd2(aA0, aA1), fadd2(aA2, aA3)));
    pB = hadd(fadd2(fadd2(aB0, aB1), fadd2(aB2, aB3)));
}

__global__ void __launch_bounds__(384, 1)
k_fused(const int* __restrict__ x, const float* __restrict__ Whh0,
        const float* __restrict__ Wih1, const float* __restrict__ Whh1,
        const float* __restrict__ bih1, const float* __restrict__ bhh1,
        float* __restrict__ hid0, float* __restrict__ hid1) {
    __shared__ __align__(16) float h0s[2][2][128];   // [parity][batch][j]
    __shared__ __align__(16) float u_s[2][2][128];
    __shared__ __align__(16) float h1s[2][2][128];
    __shared__ int x_s[2][T_];

    int tid = threadIdx.x;
    int gid = tid >> 7, j = tid & 127;
    int bA = blockIdx.x * 2, bB = bA + 1;

    // Group's weight row (full 128-wide row in 64 ull regs)
    const float* Wsel = (gid == 0) ? Whh0 : ((gid == 1) ? Wih1 : Whh1);
    ull w[64];
    const ull* Wp = (const ull*)Wsel + j * 64;
#pragma unroll
    for (int i = 0; i < 64; i++) w[i] = Wp[i];

    // Stage x for both batches; zero state buffers.
    for (int idx = tid; idx < 2 * T_; idx += 384) {
        int b = idx >> 10, t = idx & (T_ - 1);
        x_s[b][t] = x[(bA + b) * T_ + t];
    }
    for (int idx = tid; idx < 2 * 2 * 128; idx += 384) {
        ((float*)h0s)[idx] = 0.0f;
        ((float*)h1s)[idx] = 0.0f;
        ((float*)u_s)[idx] = 0.0f;
    }
    float bias_j = 0.0f;
    if (gid == 2) bias_j = bih1[j] + bhh1[j];
    __syncthreads();

    // G0 addend prefetch (2-deep)
    float pA_cur = 0.0f, pB_cur = 0.0f, pA_nxt = 0.0f, pB_nxt = 0.0f;
    if (gid == 0) {
        pA_cur = g_proj[x_s[0][0] * H_ + j];
        pB_cur = g_proj[x_s[1][0] * H_ + j];
        pA_nxt = g_proj[x_s[0][1] * H_ + j];
        pB_nxt = g_proj[x_s[1][1] * H_ + j];
    }

    float nh0A = 0.0f, nh0B = 0.0f, nh1A = 0.0f, nh1B = 0.0f;

    for (int i = 0; i < T_ + 2; i++) {
        int rp = (i - 1) & 1;   // parity of state written last iteration
        int wp = i & 1;         // parity written this iteration

        if (gid == 0) {
            if (i < T_) {
                float dA, dB;
                dot2b(h0s[rp][0], h0s[rp][1], w, dA, dB);   // Whh0 @ h0[i-1]
                nh0A = tanh_fast(dA + pA_cur);
                nh0B = tanh_fast(dB + pB_cur);
                h0s[wp][0][j] = nh0A;
                h0s[wp][1][j] = nh0B;
                pA_cur = pA_nxt; pB_cur = pB_nxt;
                int tn = (i + 2 < T_) ? (i + 2) : (T_ - 1);
                pA_nxt = g_proj[x_s[0][tn] * H_ + j];
                pB_nxt = g_proj[x_s[1][tn] * H_ + j];
            }
        } else if (gid == 1) {
            if (i >= 1 && i <= T_) {
                float uA, uB;
                dot2b(h0s[rp][0], h0s[rp][1], w, uA, uB);   // Wih1 @ h0[i-1]
                u_s[rp][0][j] = uA;                          // u[i-1] at parity (i-1)&1
                u_s[rp][1][j] = uB;
            }
        } else {
            if (i >= 2) {
                float vA, vB;
                dot2b(h1s[rp][0], h1s[rp][1], w, vA, vB);   // Whh1 @ h1[i-3]
                // u[i-2]: written at iter i-1 to parity (i-2)&1 == i&1 == wp
                nh1A = tanh_fast(u_s[wp][0][j] + vA + bias_j);
                nh1B = tanh_fast(u_s[wp][1][j] + vB + bias_j);
                h1s[wp][0][j] = nh1A;   // h1[i-2] at parity i&1
                h1s[wp][1][j] = nh1B;
                int t = i - 2;
                g_y1[((size_t)bA * T_ + t) * H_ + j] = nh1A;
                g_y1[((size_t)bB * T_ + t) * H_ + j] = nh1B;
            }
        }
        __syncthreads();
    }

    if (gid == 0) {
        hid0[bA * H_ + j] = nh0A;
        hid0[bB * H_ + j] = nh0B;
    } else if (gid == 2) {
        hid1[bA * H_ + j] = nh1A;
        hid1[bB * H_ + j] = nh1B;
    }
}

// ---------------------------------------------------------------------------
// Tensor-core fc GEMM (R8 mainloop, pre-split W planes).
// 64-row tiles: b = blockIdx>>bshift, tile = blockIdx & mask.
// ---------------------------------------------------------------------------
__device__ __forceinline__ void mma16816(float* c, const uint* a, uint b0, uint b1) {
    asm volatile(
        "mma.sync.aligned.m16n8k16.row.col.f32.bf16.bf16.f32 "
        "{%0,%1,%2,%3}, {%4,%5,%6,%7}, {%8,%9}, {%0,%1,%2,%3};"
        : "+f"(c[0]), "+f"(c[1]), "+f"(c[2]), "+f"(c[3])
        : "r"(a[0]), "r"(a[1]), "r"(a[2]), "r"(a[3]), "r"(b0), "r"(b1));
}

template <int N>
__global__ void __launch_bounds__(256, 2)
k_tgemm(const float* __restrict__ in, const uint* __restrict__ Whi,
        const uint* __restrict__ Wlo, const float* __restrict__ b1,
        float* __restrict__ out, int bshift) {
    constexpr int NTW = N / 32;
    constexpr int ST = 68;
    extern __shared__ uint sm[];
    uint* whi = sm;
    uint* wlo = whi + N * ST;
    uint* yhi = wlo + N * ST;
    uint* ylo = yhi + 64 * ST;

    int tid = threadIdx.x;
    int b = blockIdx.x >> bshift;
    int tile = blockIdx.x & ((1 << bshift) - 1);
    size_t row0 = (size_t)b * T_ + tile * 64;

    for (int i = tid; i < N * 64; i += 256) {
        int n = i >> 6, k2 = i & 63;
        whi[n * ST + k2] = Whi[i];
        wlo[n * ST + k2] = Wlo[i];
    }
    const float2* Yg = (const float2*)(in + row0 * H_);
    for (int i = tid; i < 64 * 64; i += 256) {
        int r = i >> 6, k2 = i & 63;
        uint h, l;
        split_pack(Yg[i], h, l);
        yhi[r * ST + k2] = h;
        ylo[r * ST + k2] = l;
    }
    __syncthreads();

    int wid = tid >> 5, lane = tid & 31;
    int g = lane >> 2, t = lane & 3;
    int mg = wid & 1;
    int ng = wid >> 1;

    float c[2][NTW][4];
#pragma unroll
    for (int mt = 0; mt < 2; mt++)
#pragma unroll
        for (int nt = 0; nt < NTW; nt++)
#pragma unroll
            for (int q = 0; q < 4; q++) c[mt][nt][q] = 0.0f;

#pragma unroll
    for (int ki = 0; ki < 8; ki++) {
        int kb = ki * 8;
        uint ahi[2][4], alo[2][4];
#pragma unroll
        for (int mt = 0; mt < 2; mt++) {
            int r = mg * 32 + mt * 16;
            ahi[mt][0] = yhi[(r + g) * ST + kb + t];
            ahi[mt][1] = yhi[(r + 8 + g) * ST + kb + t];
            ahi[mt][2] = yhi[(r + g) * ST + kb + 4 + t];
            ahi[mt][3] = yhi[(r + 8 + g) * ST + kb + 4 + t];
            alo[mt][0] = ylo[(r + g) * ST + kb + t];
            alo[mt][1] = ylo[(r + 8 + g) * ST + kb + t];
            alo[mt][2] = ylo[(r + g) * ST + kb + 4 + t];
            alo[mt][3] = ylo[(r + 8 + g) * ST + kb + 4 + t];
        }
#pragma unroll
        for (int nt = 0; nt < NTW; nt++) {
            int n = ng * (8 * NTW) + nt * 8;
            uint bh0 = whi[(n + g) * ST + kb + t];
            uint bh1 = whi[(n + g) * ST + kb + 4 + t];
            uint bl0 = wlo[(n + g) * ST + kb + t];
            uint bl1 = wlo[(n + g) * ST + kb + 4 + t];
#pragma unroll
            for (int mt = 0; mt < 2; mt++) {
                mma16816(c[mt][nt], ahi[mt], bh0, bh1);
                mma16816(c[mt][nt], ahi[mt], bl0, bl1);
                mma16816(c[mt][nt], alo[mt], bh0, bh1);
            }
        }
    }

#pragma unroll
    for (int nt = 0; nt < NTW; nt++) {
        int n = ng * (8 * NTW) + nt * 8 + 2 * t;
        float bx = b1[n], by = b1[n + 1];
#pragma unroll
        for (int mt = 0; mt < 2; mt++) {
            size_t r = row0 + mg * 32 + mt * 16 + g;
            float2* o0 = (float2*)(out + r * N + n);
            float2* o1 = (float2*)(out + (r + 8) * N + n);
            *o0 = make_float2(c[mt][nt][0] + bx, c[mt][nt][1] + by);
            *o1 = make_float2(c[mt][nt][2] + bx, c[mt][nt][3] + by);
        }
    }
}

// ---------------------------------------------------------------------------
extern "C" void kernel_launch(void* const* d_in, const int* in_sizes, int n_in,
                              void* d_out, int out_size) {
    const int*   x    = (const int*)d_in[0];
    const float* emb  = (const float*)d_in[1];
    const float* Wih0 = (const float*)d_in[2];
    const float* Whh0 = (const float*)d_in[3];
    const float* bih0 = (const float*)d_in[4];
    const float* bhh0 = (const float*)d_in[5];
    const float* Wih1 = (const float*)d_in[6];
    const float* Whh1 = (const float*)d_in[7];
    const float* bih1 = (const float*)d_in[8];
    const float* bhh1 = (const float*)d_in[9];
    const float* fcW  = (const float*)d_in[10];
    const float* fcb  = (const float*)d_in[11];

    float* out = (float*)d_out;
    float* hid = out + (size_t)B_ * T_ * V_;   // hidden [2,B,H] after logits

    float* y1p;  cudaGetSymbolAddress((void**)&y1p, g_y1);
    uint *wfhi, *wflo;
    cudaGetSymbolAddress((void**)&wfhi, g_Wfhi);
    cudaGetSymbolAddress((void**)&wflo, g_Wflo);

    const int smem_fc = (2 * 96 + 2 * 64) * 68 * 4;   // 87,040 B
    cudaFuncSetAttribute(k_tgemm<96>, cudaFuncAttributeMaxDynamicSharedMemorySize, smem_fc);

    k_proj<<<V_, H_>>>(emb, Wih0, bih0, bhh0);
    k_wsplit<<<24, 256>>>(fcW, wfhi, wflo, V_ * 64);
    k_fused<<<B_ / 2, 384>>>(x, Whh0, Wih1, Whh1, bih1, bhh1, hid, hid + B_ * H_);
    k_tgemm<96><<<16 * B_, 256, smem_fc>>>(y1p, wfhi, wflo, fcb, out, 4);
}

// round 16
// speedup vs baseline: 1.1421x; 1.1421x over previous
#include <cuda_runtime.h>
#include <cuda_bf16.h>
#include <math.h>

#define B_ 256
#define T_ 1024
#define V_ 96
#define H_ 128
#define SEG 8
#define SLEN (T_ / SEG)   // 128 steps per segment

typedef unsigned long long ull;
typedef unsigned int uint;

// Device-global scratch (allocation-free per harness rules)
__device__ __align__(16) float g_proj[V_ * H_];       // emb @ W_ih0^T + b_ih0 + b_hh0
__device__ __align__(16) float g_y0[B_ * T_ * H_];    // layer-0 outputs
__device__ __align__(16) float g_xp1[B_ * T_ * H_];   // y0 @ W_ih1^T + b_ih1 + b_hh1
__device__ __align__(16) float g_y1[B_ * T_ * H_];    // layer-1 outputs
__device__ __align__(16) float g_h0[B_ * H_];         // l0 h-state across segments
__device__ __align__(16) float g_h1[B_ * H_];         // l1 h-state across segments
__device__ __align__(16) uint g_Whi1[H_ * 64];        // Wih1 split hi (bf16x2, [n][64])
__device__ __align__(16) uint g_Wlo1[H_ * 64];        // Wih1 split lo
__device__ __align__(16) uint g_Wfhi[V_ * 64];        // fcW split hi
__device__ __align__(16) uint g_Wflo[V_ * 64];        // fcW split lo

__device__ __forceinline__ ull ffma2(ull a, ull b, ull c) {
    ull d;
    asm("fma.rn.f32x2 %0, %1, %2, %3;" : "=l"(d) : "l"(a), "l"(b), "l"(c));
    return d;
}
__device__ __forceinline__ ull fadd2(ull a, ull b) {
    ull d;
    asm("add.rn.f32x2 %0, %1, %2;" : "=l"(d) : "l"(a), "l"(b));
    return d;
}
__device__ __forceinline__ float hadd(ull a) {
    float x, y;
    asm("mov.b64 {%0, %1}, %2;" : "=f"(x), "=f"(y) : "l"(a));
    return x + y;
}
__device__ __forceinline__ float tanh_fast(float x) {
    float y;
    asm("tanh.approx.f32 %0, %1;" : "=f"(y) : "f"(x));
    return y;
}
__device__ __forceinline__ void split_pack(float2 v, uint& hi, uint& lo) {
    __nv_bfloat16 h0 = __float2bfloat16_rn(v.x);
    __nv_bfloat16 h1 = __float2bfloat16_rn(v.y);
    float r0 = v.x - __bfloat162float(h0);
    float r1 = v.y - __bfloat162float(h1);
    __nv_bfloat162 hp; hp.x = h0; hp.y = h1;
    __nv_bfloat162 lp = __floats2bfloat162_rn(r0, r1);
    hi = *(uint*)&hp;
    lo = *(uint*)&lp;
}

// ---------------------------------------------------------------------------
// Projected embedding table
// ---------------------------------------------------------------------------
__global__ void k_proj(const float* __restrict__ emb, const float* __restrict__ Wih0,
                       const float* __restrict__ bih0, const float* __restrict__ bhh0) {
    __shared__ float er[H_];
    int v = blockIdx.x, j = threadIdx.x;
    er[j] = emb[v * H_ + j];
    __syncthreads();
    float s = bih0[j] + bhh0[j];
    const float* wr = Wih0 + j * H_;
#pragma unroll 8
    for (int h = 0; h < H_; h++) s += er[h] * wr[h];
    g_proj[v * H_ + j] = s;
}

// Pre-split a weight matrix into bf16 hi/lo planes ([n][64] uint pairs).
__global__ void k_wsplit(const float* __restrict__ W, uint* __restrict__ hi,
                         uint* __restrict__ lo, int npairs) {
    int i = blockIdx.x * 256 + threadIdx.x;
    if (i >= npairs) return;
    uint h, l;
    split_pack(((const float2*)W)[i], h, l);
    hi[i] = h;
    lo[i] = l;
}

// ---------------------------------------------------------------------------
// Recurrence bodies (R5 form): 2 batches/CTA, 256 thr, grid B_/2 = 128.
// Thread (j = tid>>1, kh = tid&1): kh takes interleaved 16B chunks ->
// conflict-free broadcast LDS.128; one W register set (32 ull = 64 regs)
// serves both batches; one shfl.bfly reduce; ONE barrier per step;
// post-barrier gmem y stores. ~124 regs -> 2 CTAs/SM guaranteed:
// chains A+B co-resident (256 CTAs <= 296 slots) - no queueing.
// ---------------------------------------------------------------------------
__device__ __forceinline__ void load_w_ks(const float* __restrict__ W, int j, int kh, ull* w) {
    const ulonglong2* Wc = (const ulonglong2*)W + j * 32;
#pragma unroll
    for (int i = 0; i < 16; i++) {
        ulonglong2 t = Wc[2 * i + kh];
        w[2 * i] = t.x;
        w[2 * i + 1] = t.y;
    }
}

__device__ __forceinline__ void dot2(const float* __restrict__ hA, const float* __restrict__ hB,
                                     int kh, const ull* w, float& pA, float& pB) {
    const ulonglong2* a2 = (const ulonglong2*)hA;
    const ulonglong2* b2 = (const ulonglong2*)hB;
    ull aA0 = 0, aA1 = 0, aA2 = 0, aA3 = 0;
    ull aB0 = 0, aB1 = 0, aB2 = 0, aB3 = 0;
#pragma unroll
    for (int i = 0; i < 16; i += 2) {
        ulonglong2 vA0 = a2[2 * i + kh];
        ulonglong2 vB0 = b2[2 * i + kh];
        ulonglong2 vA1 = a2[2 * (i + 1) + kh];
        ulonglong2 vB1 = b2[2 * (i + 1) + kh];
        aA0 = ffma2(w[2 * i],     vA0.x, aA0);
        aB0 = ffma2(w[2 * i],     vB0.x, aB0);
        aA1 = ffma2(w[2 * i + 1], vA0.y, aA1);
        aB1 = ffma2(w[2 * i + 1], vB0.y, aB1);
        aA2 = ffma2(w[2 * i + 2], vA1.x, aA2);
        aB2 = ffma2(w[2 * i + 2], vB1.x, aB2);
        aA3 = ffma2(w[2 * i + 3], vA1.y, aA3);
        aB3 = ffma2(w[2 * i + 3], vB1.y, aB3);
    }
    float qA = hadd(fadd2(fadd2(aA0, aA1), fadd2(aA2, aA3)));
    float qB = hadd(fadd2(fadd2(aB0, aB1), fadd2(aB2, aB3)));
    qA += __shfl_xor_sync(0xffffffffu, qA, 1);
    qB += __shfl_xor_sync(0xffffffffu, qB, 1);
    pA = qA; pB = qB;
}

__global__ void __launch_bounds__(256, 2)
k_l0seg(int seg, const int* __restrict__ x, const float* __restrict__ Whh0,
        float* __restrict__ hid0) {
    __shared__ __align__(16) float h_s[2][2][128];   // [batch][parity][j]
    __shared__ int x_s[2][SLEN + 2];

    int tid = threadIdx.x;
    int j = tid >> 1, kh = tid & 1;
    int bA = blockIdx.x * 2, bB = bA + 1;
    int t0 = seg * SLEN;

    ull w[32];
    load_w_ks(Whh0, j, kh, w);

    // stage this segment's x window (+2 prefetch slots) for both batches
    for (int i = tid; i < 2 * (SLEN + 2); i += 256) {
        int b = (i < SLEN + 2) ? 0 : 1;
        int k = (i < SLEN + 2) ? i : (i - (SLEN + 2));
        int t = t0 + k;
        x_s[b][k] = x[(bA + b) * T_ + ((t < T_) ? t : (T_ - 1))];
    }
    if (tid < 128) {
        h_s[0][0][tid] = (seg == 0) ? 0.0f : g_h0[bA * H_ + tid];
        h_s[1][0][tid] = (seg == 0) ? 0.0f : g_h0[bB * H_ + tid];
    }
    __syncthreads();

    float pA_cur = g_proj[x_s[0][0] * H_ + j];
    float pB_cur = g_proj[x_s[1][0] * H_ + j];
    float pA_nxt = g_proj[x_s[0][1] * H_ + j];
    float pB_nxt = g_proj[x_s[1][1] * H_ + j];

    float nhA = 0.0f, nhB = 0.0f;
    for (int tt = 0; tt < SLEN; tt++) {
        int t = t0 + tt;
        float pA, pB;
        dot2(h_s[0][tt & 1], h_s[1][tt & 1], kh, w, pA, pB);

        nhA = tanh_fast(pA + pA_cur);
        nhB = tanh_fast(pB + pB_cur);
        if (kh == 0) {
            h_s[0][(tt + 1) & 1][j] = nhA;
            h_s[1][(tt + 1) & 1][j] = nhB;
        }

        pA_cur = pA_nxt; pB_cur = pB_nxt;
        int kn = (tt + 2 <= SLEN + 1) ? (tt + 2) : (SLEN + 1);
        pA_nxt = g_proj[x_s[0][kn] * H_ + j];
        pB_nxt = g_proj[x_s[1][kn] * H_ + j];
        __syncthreads();
        if (kh) {                                     // post-barrier stores
            g_y0[((size_t)bA * T_ + t) * H_ + j] = nhA;
            g_y0[((size_t)bB * T_ + t) * H_ + j] = nhB;
        }
    }
    if (kh == 0) {
        g_h0[bA * H_ + j] = nhA;
        g_h0[bB * H_ + j] = nhB;
        if (seg == SEG - 1) {
            hid0[bA * H_ + j] = nhA;
            hid0[bB * H_ + j] = nhB;
        }
    }
}

__global__ void __launch_bounds__(256, 2)
k_l1seg(int seg, const float* __restrict__ Whh1, float* __restrict__ hid1) {
    __shared__ __align__(16) float h_s[2][2][128];

    int tid = threadIdx.x;
    int j = tid >> 1, kh = tid & 1;
    int bA = blockIdx.x * 2, bB = bA + 1;
    int t0 = seg * SLEN;

    ull w[32];
    load_w_ks(Whh1, j, kh, w);

    if (tid < 128) {
        h_s[0][0][tid] = (seg == 0) ? 0.0f : g_h1[bA * H_ + tid];
        h_s[1][0][tid] = (seg == 0) ? 0.0f : g_h1[bB * H_ + tid];
    }
    __syncthreads();

    const float* xpA = g_xp1 + ((size_t)bA * T_ + t0) * H_ + j;
    const float* xpB = g_xp1 + ((size_t)bB * T_ + t0) * H_ + j;
    float pA_cur = xpA[0], pB_cur = xpB[0];
    float pA_nxt = xpA[H_], pB_nxt = xpB[H_];

    float nhA = 0.0f, nhB = 0.0f;
    for (int tt = 0; tt < SLEN; tt++) {
        int t = t0 + tt;
        float pA, pB;
        dot2(h_s[0][tt & 1], h_s[1][tt & 1], kh, w, pA, pB);

        nhA = tanh_fast(pA + pA_cur);
        nhB = tanh_fast(pB + pB_cur);
        if (kh == 0) {
            h_s[0][(tt + 1) & 1][j] = nhA;
            h_s[1][(tt + 1) & 1][j] = nhB;
        }

        pA_cur = pA_nxt; pB_cur = pB_nxt;
        int tn = (t + 2 < T_) ? (t + 2) : (T_ - 1);   // may read ahead; value unused past seg end
        pA_nxt = xpA[(size_t)(tn - t0) * H_];
        pB_nxt = xpB[(size_t)(tn - t0) * H_];
        __syncthreads();
        if (kh) {
            g_y1[((size_t)bA * T_ + t) * H_ + j] = nhA;
            g_y1[((size_t)bB * T_ + t) * H_ + j] = nhB;
        }
    }
    if (kh == 0) {
        g_h1[bA * H_ + j] = nhA;
        g_h1[bB * H_ + j] = nhB;
        if (seg == SEG - 1) {
            hid1[bA * H_ + j] = nhA;
            hid1[bB * H_ + j] = nhB;
        }
    }
}

// ---------------------------------------------------------------------------
// Tensor-core GEMM (R8 mainloop, pre-split W planes).
// Tiles: 64 rows at (blockIdx>>bshift)*T_ + tstart + (blockIdx&mask)*64.
// ---------------------------------------------------------------------------
__device__ __forceinline__ void mma16816(float* c, const uint* a, uint b0, uint b1) {
    asm volatile(
        "mma.sync.aligned.m16n8k16.row.col.f32.bf16.bf16.f32 "
        "{%0,%1,%2,%3}, {%4,%5,%6,%7}, {%8,%9}, {%0,%1,%2,%3};"
        : "+f"(c[0]), "+f"(c[1]), "+f"(c[2]), "+f"(c[3])
        : "r"(a[0]), "r"(a[1]), "r"(a[2]), "r"(a[3]), "r"(b0), "r"(b1));
}

template <int N>
__global__ void __launch_bounds__(256, 2)
k_tgemm(const float* __restrict__ in, const uint* __restrict__ Whi,
        const uint* __restrict__ Wlo, const float* __restrict__ b1,
        const float* __restrict__ b2, float* __restrict__ out,
        int tstart, int bshift) {
    constexpr int NTW = N / 32;
    constexpr int ST = 68;
    extern __shared__ uint sm[];
    uint* whi = sm;
    uint* wlo = whi + N * ST;
    uint* yhi = wlo + N * ST;
    uint* ylo = yhi + 64 * ST;

    int tid = threadIdx.x;
    int b = blockIdx.x >> bshift;
    int tile = blockIdx.x & ((1 << bshift) - 1);
    size_t row0 = (size_t)b * T_ + tstart + tile * 64;

    for (int i = tid; i < N * 64; i += 256) {
        int n = i >> 6, k2 = i & 63;
        whi[n * ST + k2] = Whi[i];
        wlo[n * ST + k2] = Wlo[i];
    }
    const float2* Yg = (const float2*)(in + row0 * H_);
    for (int i = tid; i < 64 * 64; i += 256) {
        int r = i >> 6, k2 = i & 63;
        uint h, l;
        split_pack(Yg[i], h, l);
        yhi[r * ST + k2] = h;
        ylo[r * ST + k2] = l;
    }
    __syncthreads();

    int wid = tid >> 5, lane = tid & 31;
    int g = lane >> 2, t = lane & 3;
    int mg = wid & 1;
    int ng = wid >> 1;

    float c[2][NTW][4];
#pragma unroll
    for (int mt = 0; mt < 2; mt++)
#pragma unroll
        for (int nt = 0; nt < NTW; nt++)
#pragma unroll
            for (int q = 0; q < 4; q++) c[mt][nt][q] = 0.0f;

#pragma unroll
    for (int ki = 0; ki < 8; ki++) {
        int kb = ki * 8;
        uint ahi[2][4], alo[2][4];
#pragma unroll
        for (int mt = 0; mt < 2; mt++) {
            int r = mg * 32 + mt * 16;
            ahi[mt][0] = yhi[(r + g) * ST + kb + t];
            ahi[mt][1] = yhi[(r + 8 + g) * ST + kb + t];
            ahi[mt][2] = yhi[(r + g) * ST + kb + 4 + t];
            ahi[mt][3] = yhi[(r + 8 + g) * ST + kb + 4 + t];
            alo[mt][0] = ylo[(r + g) * ST + kb + t];
            alo[mt][1] = ylo[(r + 8 + g) * ST + kb + t];
            alo[mt][2] = ylo[(r + g) * ST + kb + 4 + t];
            alo[mt][3] = ylo[(r + 8 + g) * ST + kb + 4 + t];
        }
#pragma unroll
        for (int nt = 0; nt < NTW; nt++) {
            int n = ng * (8 * NTW) + nt * 8;
            uint bh0 = whi[(n + g) * ST + kb + t];
            uint bh1 = whi[(n + g) * ST + kb + 4 + t];
            uint bl0 = wlo[(n + g) * ST + kb + t];
            uint bl1 = wlo[(n + g) * ST + kb + 4 + t];
#pragma unroll
            for (int mt = 0; mt < 2; mt++) {
                mma16816(c[mt][nt], ahi[mt], bh0, bh1);
                mma16816(c[mt][nt], ahi[mt], bl0, bl1);
                mma16816(c[mt][nt], alo[mt], bh0, bh1);
            }
        }
    }

#pragma unroll
    for (int nt = 0; nt < NTW; nt++) {
        int n = ng * (8 * NTW) + nt * 8 + 2 * t;
        float bx = b1[n], by = b1[n + 1];
        if (b2) { bx += b2[n]; by += b2[n + 1]; }
#pragma unroll
        for (int mt = 0; mt < 2; mt++) {
            size_t r = row0 + mg * 32 + mt * 16 + g;
            float2* o0 = (float2*)(out + r * N + n);
            float2* o1 = (float2*)(out + (r + 8) * N + n);
            *o0 = make_float2(c[mt][nt][0] + bx, c[mt][nt][1] + by);
            *o1 = make_float2(c[mt][nt][2] + bx, c[mt][nt][3] + by);
        }
    }
}

// ---------------------------------------------------------------------------
// Streams/events: created ONCE on the first (correctness) call. Identical
// launch DAG every call (R13 structure).
// ---------------------------------------------------------------------------
static bool s_init = false;
static cudaStream_t sB, sC, sD;
static cudaEvent_t eA[SEG], eB[SEG], eC[SEG], eEnd;

extern "C" void kernel_launch(void* const* d_in, const int* in_sizes, int n_in,
                              void* d_out, int out_size) {
    const int*   x    = (const int*)d_in[0];
    const float* emb  = (const float*)d_in[1];
    const float* Wih0 = (const float*)d_in[2];
    const float* Whh0 = (const float*)d_in[3];
    const float* bih0 = (const float*)d_in[4];
    const float* bhh0 = (const float*)d_in[5];
    const float* Wih1 = (const float*)d_in[6];
    const float* Whh1 = (const float*)d_in[7];
    const float* bih1 = (const float*)d_in[8];
    const float* bhh1 = (const float*)d_in[9];
    const float* fcW  = (const float*)d_in[10];
    const float* fcb  = (const float*)d_in[11];

    float* out = (float*)d_out;
    float* hid = out + (size_t)B_ * T_ * V_;   // hidden [2,B,H] after logits

    float* y0p;  cudaGetSymbolAddress((void**)&y0p,  g_y0);
    float* xp1p; cudaGetSymbolAddress((void**)&xp1p, g_xp1);
    float* y1p;  cudaGetSymbolAddress((void**)&y1p,  g_y1);
    uint *whi1, *wlo1, *wfhi, *wflo;
    cudaGetSymbolAddress((void**)&whi1, g_Whi1);
    cudaGetSymbolAddress((void**)&wlo1, g_Wlo1);
    cudaGetSymbolAddress((void**)&wfhi, g_Wfhi);
    cudaGetSymbolAddress((void**)&wflo, g_Wflo);

    const int smem_xp = (2 * 128 + 2 * 64) * 68 * 4;   // 104,448 B
    const int smem_fc = (2 * 96  + 2 * 64) * 68 * 4;   //  87,040 B

    if (!s_init) {
        cudaFuncSetAttribute(k_tgemm<128>, cudaFuncAttributeMaxDynamicSharedMemorySize, smem_xp);
        cudaFuncSetAttribute(k_tgemm<96>,  cudaFuncAttributeMaxDynamicSharedMemorySize, smem_fc);
        int prLo, prHi;
        cudaDeviceGetStreamPriorityRange(&prLo, &prHi);
        cudaStreamCreateWithFlags(&sB, cudaStreamNonBlocking);
        cudaStreamCreateWithFlags(&sC, cudaStreamNonBlocking);
        cudaStreamCreateWithPriority(&sD, cudaStreamNonBlocking, prLo);   // fc: slack
        for (int s = 0; s < SEG; s++) {
            cudaEventCreateWithFlags(&eA[s], cudaEventDisableTiming);
            cudaEventCreateWithFlags(&eB[s], cudaEventDisableTiming);
            cudaEventCreateWithFlags(&eC[s], cudaEventDisableTiming);
        }
        cudaEventCreateWithFlags(&eEnd, cudaEventDisableTiming);
        s_init = true;
    }

    // Chain A (stream 0): proj + W pre-splits, then l0 segments back-to-back.
    k_proj<<<V_, H_>>>(emb, Wih0, bih0, bhh0);
    k_wsplit<<<32, 256>>>(Wih1, whi1, wlo1, H_ * 64);
    k_wsplit<<<24, 256>>>(fcW,  wfhi, wflo, V_ * 64);
    for (int s = 0; s < SEG; s++) {
        k_l0seg<<<B_ / 2, 256>>>(s, x, Whh0, hid);
        cudaEventRecord(eA[s], 0);
        // Chain C: xp1 GEMM for segment s (after l0 seg s).
        cudaStreamWaitEvent(sC, eA[s], 0);
        k_tgemm<128><<<2 * B_, 256, smem_xp, sC>>>(y0p, whi1, wlo1, bih1, bhh1,
                                                   xp1p, s * SLEN, 1);
        cudaEventRecord(eC[s], sC);
        // Chain B (spine): l1 segment s after its xp chunk.
        cudaStreamWaitEvent(sB, eC[s], 0);
        k_l1seg<<<B_ / 2, 256, 0, sB>>>(s, Whh1, hid + B_ * H_);
        cudaEventRecord(eB[s], sB);
        // Chain D: fc GEMM for segment s (after l1 seg s), low priority.
        cudaStreamWaitEvent(sD, eB[s], 0);
        k_tgemm<96><<<2 * B_, 256, smem_fc, sD>>>(y1p, wfhi, wflo, fcb, nullptr,
                                                  out, s * SLEN, 1);
    }
    cudaEventRecord(eEnd, sD);
    cudaStreamWaitEvent(0, eEnd, 0);
}

// round 17
// speedup vs baseline: 1.2313x; 1.0781x over previous
#include <cuda_runtime.h>
#include <cuda_bf16.h>
#include <math.h>

#define B_ 256
#define T_ 1024
#define V_ 96
#define H_ 128
#define SEG 8
#define SLEN (T_ / SEG)   // 128 steps per segment

typedef unsigned long long ull;
typedef unsigned int uint;

// Device-global scratch (allocation-free per harness rules)
__device__ __align__(16) float g_proj[V_ * H_];       // emb @ W_ih0^T + b_ih0 + b_hh0
__device__ __align__(16) float g_y0[B_ * T_ * H_];    // layer-0 outputs
__device__ __align__(16) float g_xp1[B_ * T_ * H_];   // y0 @ W_ih1^T + b_ih1 + b_hh1
__device__ __align__(16) float g_y1[B_ * T_ * H_];    // layer-1 outputs
__device__ __align__(16) float g_h0[B_ * H_];         // l0 h-state across segments
__device__ __align__(16) float g_h1[B_ * H_];         // l1 h-state across segments
__device__ __align__(16) uint g_Whi1[H_ * 64];        // Wih1 split hi (bf16x2, [n][64])
__device__ __align__(16) uint g_Wlo1[H_ * 64];        // Wih1 split lo
__device__ __align__(16) uint g_Wfhi[V_ * 64];        // fcW split hi
__device__ __align__(16) uint g_Wflo[V_ * 64];        // fcW split lo

__device__ __forceinline__ ull ffma2(ull a, ull b, ull c) {
    ull d;
    asm("fma.rn.f32x2 %0, %1, %2, %3;" : "=l"(d) : "l"(a), "l"(b), "l"(c));
    return d;
}
__device__ __forceinline__ float hadd(ull a) {
    float x, y;
    asm("mov.b64 {%0, %1}, %2;" : "=f"(x), "=f"(y) : "l"(a));
    return x + y;
}
__device__ __forceinline__ float tanh_fast(float x) {
    float y;
    asm("tanh.approx.f32 %0, %1;" : "=f"(y) : "f"(x));
    return y;
}
__device__ __forceinline__ void split_pack(float2 v, uint& hi, uint& lo) {
    __nv_bfloat16 h0 = __float2bfloat16_rn(v.x);
    __nv_bfloat16 h1 = __float2bfloat16_rn(v.y);
    float r0 = v.x - __bfloat162float(h0);
    float r1 = v.y - __bfloat162float(h1);
    __nv_bfloat162 hp; hp.x = h0; hp.y = h1;
    __nv_bfloat162 lp = __floats2bfloat162_rn(r0, r1);
    hi = *(uint*)&hp;
    lo = *(uint*)&lp;
}

// ---------------------------------------------------------------------------
// Projected embedding table
// ---------------------------------------------------------------------------
__global__ void k_proj(const float* __restrict__ emb, const float* __restrict__ Wih0,
                       const float* __restrict__ bih0, const float* __restrict__ bhh0) {
    __shared__ float er[H_];
    int v = blockIdx.x, j = threadIdx.x;
    er[j] = emb[v * H_ + j];
    __syncthreads();
    float s = bih0[j] + bhh0[j];
    const float* wr = Wih0 + j * H_;
#pragma unroll 8
    for (int h = 0; h < H_; h++) s += er[h] * wr[h];
    g_proj[v * H_ + j] = s;
}

// Pre-split a weight matrix into bf16 hi/lo planes ([n][64] uint pairs).
__global__ void k_wsplit(const float* __restrict__ W, uint* __restrict__ hi,
                         uint* __restrict__ lo, int npairs) {
    int i = blockIdx.x * 256 + threadIdx.x;
    if (i >= npairs) return;
    uint h, l;
    split_pack(((const float2*)W)[i], h, l);
    hi[i] = h;
    lo[i] = l;
}

// ---------------------------------------------------------------------------
// Segmented recurrence (R4 body) + 8-step register-history batched y stores:
// the STG->barrier drain is paid once per 8 steps instead of every step.
// ---------------------------------------------------------------------------
__global__ void __launch_bounds__(128, 2)
k_l0seg(int seg, const int* __restrict__ x, const float* __restrict__ Whh0,
        float* __restrict__ hid0) {
    __shared__ __align__(16) float h_s[2][128];
    __shared__ int x_s[SLEN + 2];

    int j = threadIdx.x;
    int b = blockIdx.x;
    int t0 = seg * SLEN;

    ull w[64];
    const ull* Wp = (const ull*)Whh0 + j * 64;
#pragma unroll
    for (int i = 0; i < 64; i++) w[i] = Wp[i];

    for (int i = j; i < SLEN + 2; i += 128) {
        int t = t0 + i;
        x_s[i] = x[b * T_ + ((t < T_) ? t : (T_ - 1))];
    }
    h_s[0][j] = (seg == 0) ? 0.0f : g_h0[b * H_ + j];
    __syncthreads();

    float p_cur = g_proj[x_s[0] * H_ + j];
    float p_nxt = g_proj[x_s[1] * H_ + j];

    float hist[8];
    float nh = 0.0f;
#pragma unroll 8
    for (int tt = 0; tt < SLEN; tt++) {
        const ulonglong2* h2 = (const ulonglong2*)h_s[tt & 1];
        ull a0 = 0, a1 = 0, a2 = 0, a3 = 0;
#pragma unroll
        for (int i = 0; i < 32; i += 2) {
            ulonglong2 hv = h2[i];
            a0 = ffma2(w[2 * i],     hv.x, a0);
            a1 = ffma2(w[2 * i + 1], hv.y, a1);
            ulonglong2 hw = h2[i + 1];
            a2 = ffma2(w[2 * i + 2], hw.x, a2);
            a3 = ffma2(w[2 * i + 3], hw.y, a3);
        }
        ull s01, s23, s;
        asm("add.rn.f32x2 %0, %1, %2;" : "=l"(s01) : "l"(a0), "l"(a1));
        asm("add.rn.f32x2 %0, %1, %2;" : "=l"(s23) : "l"(a2), "l"(a3));
        asm("add.rn.f32x2 %0, %1, %2;" : "=l"(s)   : "l"(s01), "l"(s23));
        float p = hadd(s);

        nh = tanh_fast(p + p_cur);
        h_s[(tt + 1) & 1][j] = nh;
        hist[tt & 7] = nh;

        p_cur = p_nxt;
        int kn = (tt + 2 <= SLEN + 1) ? (tt + 2) : (SLEN + 1);
        p_nxt = g_proj[x_s[kn] * H_ + j];
        __syncthreads();

        if ((tt & 7) == 7) {          // batched post-barrier stores (8 steps)
            float* dst = &g_y0[((size_t)b * T_ + (t0 + tt - 7)) * H_ + j];
#pragma unroll
            for (int q = 0; q < 8; q++) dst[(size_t)q * H_] = hist[q];
        }
    }
    g_h0[b * H_ + j] = nh;
    if (seg == SEG - 1) hid0[b * H_ + j] = nh;
}

__global__ void __launch_bounds__(128, 2)
k_l1seg(int seg, const float* __restrict__ Whh1, float* __restrict__ hid1) {
    __shared__ __align__(16) float h_s[2][128];

    int j = threadIdx.x;
    int b = blockIdx.x;
    int t0 = seg * SLEN;

    ull w[64];
    const ull* Wp = (const ull*)Whh1 + j * 64;
#pragma unroll
    for (int i = 0; i < 64; i++) w[i] = Wp[i];

    h_s[0][j] = (seg == 0) ? 0.0f : g_h1[b * H_ + j];
    __syncthreads();

    const float* xp = g_xp1 + (size_t)b * T_ * H_ + j;
    float p_cur = xp[(size_t)t0 * H_];
    float p_nxt = xp[(size_t)(t0 + 1) * H_];

    float hist[8];
    float nh = 0.0f;
#pragma unroll 8
    for (int tt = 0; tt < SLEN; tt++) {
        int t = t0 + tt;
        const ulonglong2* h2 = (const ulonglong2*)h_s[tt & 1];
        ull a0 = 0, a1 = 0, a2 = 0, a3 = 0;
#pragma unroll
        for (int i = 0; i < 32; i += 2) {
            ulonglong2 hv = h2[i];
            a0 = ffma2(w[2 * i],     hv.x, a0);
            a1 = ffma2(w[2 * i + 1], hv.y, a1);
            ulonglong2 hw = h2[i + 1];
            a2 = ffma2(w[2 * i + 2], hw.x, a2);
            a3 = ffma2(w[2 * i + 3], hw.y, a3);
        }
        ull s01, s23, s;
        asm("add.rn.f32x2 %0, %1, %2;" : "=l"(s01) : "l"(a0), "l"(a1));
        asm("add.rn.f32x2 %0, %1, %2;" : "=l"(s23) : "l"(a2), "l"(a3));
        asm("add.rn.f32x2 %0, %1, %2;" : "=l"(s)   : "l"(s01), "l"(s23));
        float p = hadd(s);

        nh = tanh_fast(p + p_cur);
        h_s[(tt + 1) & 1][j] = nh;
        hist[tt & 7] = nh;

        p_cur = p_nxt;
        int tn = (t + 2 < T_) ? (t + 2) : (T_ - 1);
        p_nxt = xp[(size_t)tn * H_];
        __syncthreads();

        if ((tt & 7) == 7) {
            float* dst = &g_y1[((size_t)b * T_ + (t - 7)) * H_ + j];
#pragma unroll
            for (int q = 0; q < 8; q++) dst[(size_t)q * H_] = hist[q];
        }
    }
    g_h1[b * H_ + j] = nh;
    if (seg == SEG - 1) hid1[b * H_ + j] = nh;
}

// ---------------------------------------------------------------------------
// Tensor-core GEMM (R8 mainloop, pre-split W planes).
// Tiles: 64 rows at (blockIdx>>bshift)*T_ + tstart + (blockIdx&mask)*64.
// ---------------------------------------------------------------------------
__device__ __forceinline__ void mma16816(float* c, const uint* a, uint b0, uint b1) {
    asm volatile(
        "mma.sync.aligned.m16n8k16.row.col.f32.bf16.bf16.f32 "
        "{%0,%1,%2,%3}, {%4,%5,%6,%7}, {%8,%9}, {%0,%1,%2,%3};"
        : "+f"(c[0]), "+f"(c[1]), "+f"(c[2]), "+f"(c[3])
        : "r"(a[0]), "r"(a[1]), "r"(a[2]), "r"(a[3]), "r"(b0), "r"(b1));
}

template <int N>
__global__ void __launch_bounds__(256, 2)
k_tgemm(const float* __restrict__ in, const uint* __restrict__ Whi,
        const uint* __restrict__ Wlo, const float* __restrict__ b1,
        const float* __restrict__ b2, float* __restrict__ out,
        int tstart, int bshift) {
    constexpr int NTW = N / 32;
    constexpr int ST = 68;
    extern __shared__ uint sm[];
    uint* whi = sm;
    uint* wlo = whi + N * ST;
    uint* yhi = wlo + N * ST;
    uint* ylo = yhi + 64 * ST;

    int tid = threadIdx.x;
    int b = blockIdx.x >> bshift;
    int tile = blockIdx.x & ((1 << bshift) - 1);
    size_t row0 = (size_t)b * T_ + tstart + tile * 64;

    for (int i = tid; i < N * 64; i += 256) {
        int n = i >> 6, k2 = i & 63;
        whi[n * ST + k2] = Whi[i];
        wlo[n * ST + k2] = Wlo[i];
    }
    const float2* Yg = (const float2*)(in + row0 * H_);
    for (int i = tid; i < 64 * 64; i += 256) {
        int r = i >> 6, k2 = i & 63;
        uint h, l;
        split_pack(Yg[i], h, l);
        yhi[r * ST + k2] = h;
        ylo[r * ST + k2] = l;
    }
    __syncthreads();

    int wid = tid >> 5, lane = tid & 31;
    int g = lane >> 2, t = lane & 3;
    int mg = wid & 1;
    int ng = wid >> 1;

    float c[2][NTW][4];
#pragma unroll
    for (int mt = 0; mt < 2; mt++)
#pragma unroll
        for (int nt = 0; nt < NTW; nt++)
#pragma unroll
            for (int q = 0; q < 4; q++) c[mt][nt][q] = 0.0f;

#pragma unroll
    for (int ki = 0; ki < 8; ki++) {
        int kb = ki * 8;
        uint ahi[2][4], alo[2][4];
#pragma unroll
        for (int mt = 0; mt < 2; mt++) {
            int r = mg * 32 + mt * 16;
            ahi[mt][0] = yhi[(r + g) * ST + kb + t];
            ahi[mt][1] = yhi[(r + 8 + g) * ST + kb + t];
            ahi[mt][2] = yhi[(r + g) * ST + kb + 4 + t];
            ahi[mt][3] = yhi[(r + 8 + g) * ST + kb + 4 + t];
            alo[mt][0] = ylo[(r + g) * ST + kb + t];
            alo[mt][1] = ylo[(r + 8 + g) * ST + kb + t];
            alo[mt][2] = ylo[(r + g) * ST + kb + 4 + t];
            alo[mt][3] = ylo[(r + 8 + g) * ST + kb + 4 + t];
        }
#pragma unroll
        for (int nt = 0; nt < NTW; nt++) {
            int n = ng * (8 * NTW) + nt * 8;
            uint bh0 = whi[(n + g) * ST + kb + t];
            uint bh1 = whi[(n + g) * ST + kb + 4 + t];
            uint bl0 = wlo[(n + g) * ST + kb + t];
            uint bl1 = wlo[(n + g) * ST + kb + 4 + t];
#pragma unroll
            for (int mt = 0; mt < 2; mt++) {
                mma16816(c[mt][nt], ahi[mt], bh0, bh1);
                mma16816(c[mt][nt], ahi[mt], bl0, bl1);
                mma16816(c[mt][nt], alo[mt], bh0, bh1);
            }
        }
    }

#pragma unroll
    for (int nt = 0; nt < NTW; nt++) {
        int n = ng * (8 * NTW) + nt * 8 + 2 * t;
        float bx = b1[n], by = b1[n + 1];
        if (b2) { bx += b2[n]; by += b2[n + 1]; }
#pragma unroll
        for (int mt = 0; mt < 2; mt++) {
            size_t r = row0 + mg * 32 + mt * 16 + g;
            float2* o0 = (float2*)(out + r * N + n);
            float2* o1 = (float2*)(out + (r + 8) * N + n);
            *o0 = make_float2(c[mt][nt][0] + bx, c[mt][nt][1] + by);
            *o1 = make_float2(c[mt][nt][2] + bx, c[mt][nt][3] + by);
        }
    }
}

// ---------------------------------------------------------------------------
// Streams/events: created ONCE on the first (correctness) call. Identical
// launch DAG every call (R13 structure).
// ---------------------------------------------------------------------------
static bool s_init = false;
static cudaStream_t sB, sC, sD;
static cudaEvent_t eA[SEG], eB[SEG], eC[SEG], eEnd;

extern "C" void kernel_launch(void* const* d_in, const int* in_sizes, int n_in,
                              void* d_out, int out_size) {
    const int*   x    = (const int*)d_in[0];
    const float* emb  = (const float*)d_in[1];
    const float* Wih0 = (const float*)d_in[2];
    const float* Whh0 = (const float*)d_in[3];
    const float* bih0 = (const float*)d_in[4];
    const float* bhh0 = (const float*)d_in[5];
    const float* Wih1 = (const float*)d_in[6];
    const float* Whh1 = (const float*)d_in[7];
    const float* bih1 = (const float*)d_in[8];
    const float* bhh1 = (const float*)d_in[9];
    const float* fcW  = (const float*)d_in[10];
    const float* fcb  = (const float*)d_in[11];

    float* out = (float*)d_out;
    float* hid = out + (size_t)B_ * T_ * V_;   // hidden [2,B,H] after logits

    float* y0p;  cudaGetSymbolAddress((void**)&y0p,  g_y0);
    float* xp1p; cudaGetSymbolAddress((void**)&xp1p, g_xp1);
    float* y1p;  cudaGetSymbolAddress((void**)&y1p,  g_y1);
    uint *whi1, *wlo1, *wfhi, *wflo;
    cudaGetSymbolAddress((void**)&whi1, g_Whi1);
    cudaGetSymbolAddress((void**)&wlo1, g_Wlo1);
    cudaGetSymbolAddress((void**)&wfhi, g_Wfhi);
    cudaGetSymbolAddress((void**)&wflo, g_Wflo);

    const int smem_xp = (2 * 128 + 2 * 64) * 68 * 4;   // 104,448 B
    const int smem_fc = (2 * 96  + 2 * 64) * 68 * 4;   //  87,040 B

    if (!s_init) {
        cudaFuncSetAttribute(k_tgemm<128>, cudaFuncAttributeMaxDynamicSharedMemorySize, smem_xp);
        cudaFuncSetAttribute(k_tgemm<96>,  cudaFuncAttributeMaxDynamicSharedMemorySize, smem_fc);
        int prLo, prHi;
        cudaDeviceGetStreamPriorityRange(&prLo, &prHi);
        cudaStreamCreateWithFlags(&sB, cudaStreamNonBlocking);
        cudaStreamCreateWithFlags(&sC, cudaStreamNonBlocking);
        cudaStreamCreateWithPriority(&sD, cudaStreamNonBlocking, prLo);   // fc: slack
        for (int s = 0; s < SEG; s++) {
            cudaEventCreateWithFlags(&eA[s], cudaEventDisableTiming);
            cudaEventCreateWithFlags(&eB[s], cudaEventDisableTiming);
            cudaEventCreateWithFlags(&eC[s], cudaEventDisableTiming);
        }
        cudaEventCreateWithFlags(&eEnd, cudaEventDisableTiming);
        s_init = true;
    }

    // Chain A (stream 0): proj + W pre-splits, then l0 segments back-to-back.
    k_proj<<<V_, H_>>>(emb, Wih0, bih0, bhh0);
    k_wsplit<<<32, 256>>>(Wih1, whi1, wlo1, H_ * 64);
    k_wsplit<<<24, 256>>>(fcW,  wfhi, wflo, V_ * 64);
    for (int s = 0; s < SEG; s++) {
        k_l0seg<<<B_, 128>>>(s, x, Whh0, hid);
        cudaEventRecord(eA[s], 0);
        // Chain C: xp1 GEMM for segment s (after l0 seg s).
        cudaStreamWaitEvent(sC, eA[s], 0);
        k_tgemm<128><<<2 * B_, 256, smem_xp, sC>>>(y0p, whi1, wlo1, bih1, bhh1,
                                                   xp1p, s * SLEN, 1);
        cudaEventRecord(eC[s], sC);
        // Chain B (spine): l1 segment s after its xp chunk.
        cudaStreamWaitEvent(sB, eC[s], 0);
        k_l1seg<<<B_, 128, 0, sB>>>(s, Whh1, hid + B_ * H_);
        cudaEventRecord(eB[s], sB);
        // Chain D: fc GEMM for segment s (after l1 seg s), low priority.
        cudaStreamWaitEvent(sD, eB[s], 0);
        k_tgemm<96><<<2 * B_, 256, smem_fc, sD>>>(y1p, wfhi, wflo, fcb, nullptr,
                                                  out, s * SLEN, 1);
    }
    cudaEventRecord(eEnd, sD);
    cudaStreamWaitEvent(0, eEnd, 0);
}